// round 12
// baseline (speedup 1.0000x reference)
#include <cuda_runtime.h>
#include <cuda_fp16.h>
#include <cstdint>

// Conv2d 3x3 s1 p1 via mma.sync m16n8k16 FP16 (f32 accum) implicit GEMM.
// 256-thread CTAs, CTA tile 128oc x 128px, 8 warps with 64x32 warp tiles
// (4 warps/SMSP for latency hiding). K order: chunk(64ch), tap, k16; all 9 taps
// of a chunk read one union window staged once (32 cpairs x 352 words, stride
// 360). 2 syncs total. A: prepass packs per-thread fragments (consumption
// order), LDG.128 per k16. B: prepass packs fp16 channel-pairs, zero-padded.

#define HW    3136
#define PHW   3364            // 58*58
#define CIN   128
#define COUT  256
#define KTOT  1152
#define LDW   360             // window row stride (words); 360 mod 32 = 8
#define CHUNKW (32*LDW)       // 11520 words per chunk window
#define SMEM_BYTES ((2*CHUNKW + 64)*4)   // 92416 B

__device__ __align__(16) uint32_t g_wf[72 * 2 * 2 * 32 * 16];     // frags, consumption order
__device__ __align__(16) uint32_t g_xh[32 * 64 * PHW + 1024];     // packed fp16 x

// word w: reg=w&3, mf=(w>>2)&3, lane=(w>>4)&31, wmg=(w>>9)&1, oct=(w>>10)&1, kt16=w>>11
// kt16 = chunk*36 + tap*4 + h ; channels c = chunk*64 + h*16 + klocal ; rs = tap
__global__ void wf_kernel(const float* __restrict__ W) {
    const int w = blockIdx.x * 256 + threadIdx.x;
    const int reg = w & 3, mf = (w >> 2) & 3, lane = (w >> 4) & 31;
    const int wmg = (w >> 9) & 1, oct = (w >> 10) & 1, kt = w >> 11;
    const int chunk = kt / 36, rem = kt - chunk * 36;
    const int tap = rem >> 2, h = rem & 3;
    const int r = lane >> 2, cq = lane & 3;
    const int oc = oct * 128 + wmg * 64 + mf * 16 + r + (reg & 1) * 8;
    const int klocal = 2 * cq + ((reg & 2) ? 8 : 0);
    const int c = chunk * 64 + h * 16 + klocal;
    const __half2 hv = __floats2half2_rn(W[oc * KTOT + c * 9 + tap],
                                         W[oc * KTOT + (c + 1) * 9 + tap]);
    g_wf[w] = *reinterpret_cast<const uint32_t*>(&hv);
}

__global__ void xh_kernel(const float* __restrict__ x) {
    const int idx = blockIdx.x * 256 + threadIdx.x;
    const int cell = idx % PHW;
    const int cp = (idx / PHW) & 63;
    const int ni = idx / (PHW * 64);
    const int ph = cell / 58, pw = cell - ph * 58;
    float lo = 0.0f, hi = 0.0f;
    if (ph >= 1 && ph <= 56 && pw >= 1 && pw <= 56) {
        const size_t base = ((size_t)ni * CIN + 2 * cp) * HW + (ph - 1) * 56 + (pw - 1);
        lo = x[base];
        hi = x[base + HW];
    }
    const __half2 h = __floats2half2_rn(lo, hi);
    g_xh[idx] = *reinterpret_cast<const uint32_t*>(&h);
}

__device__ __forceinline__ void cp16(uint32_t d, const void* s) {
    asm volatile("cp.async.cg.shared.global [%0], [%1], 16;" :: "r"(d), "l"(s));
}
#define CP_COMMIT asm volatile("cp.async.commit_group;" ::: "memory")
#define CP_WAIT(n) asm volatile("cp.async.wait_group %0;" :: "n"(n) : "memory")

#define MMA16(acc, a, b0, b1) \
    asm volatile("mma.sync.aligned.m16n8k16.row.col.f32.f16.f16.f32 " \
        "{%0,%1,%2,%3}, {%4,%5,%6,%7}, {%8,%9}, {%0,%1,%2,%3};" \
        : "+f"((acc)[0]), "+f"((acc)[1]), "+f"((acc)[2]), "+f"((acc)[3]) \
        : "r"((a)[0]), "r"((a)[1]), "r"((a)[2]), "r"((a)[3]), "r"(b0), "r"(b1))

__global__ void __launch_bounds__(256, 2)
conv_mma(const float* __restrict__ bias, float* __restrict__ out)
{
    extern __shared__ uint32_t smW[];
    const uint32_t smb = (uint32_t)__cvta_generic_to_shared(smW);
    const int tid  = threadIdx.x;
    const int lane = tid & 31;
    const int wid  = tid >> 5;            // 0..7
    const int r    = lane >> 2, cq = lane & 3;
    const int p0   = blockIdx.x * 128;
    const int ni   = blockIdx.y;
    const int oct  = blockIdx.z;
    const int wmg  = wid & 1;
    const int wn0  = (wid >> 1) * 32;     // 0,32,64,96

    const int oh0 = p0 / 56;
    const int abase = (oh0 * 58) & ~3;
    const int am0   = oh0 * 58 - abase;

    // per-thread B pixel offsets relative to window start (4 nf groups of 8 px)
    int pxr[4];
#pragma unroll
    for (int nf = 0; nf < 4; nf++) {
        int px = p0 + wn0 + nf * 8 + r;
        if (px >= HW) px = HW - 1;
        const int oh = px / 56, ow = px - oh * 56;
        pxr[nf] = oh * 58 + ow - oh0 * 58 + am0;
    }

    const uint32_t* xim = g_xh + (size_t)ni * (64 * PHW);

    float acc[4][4][4];
#pragma unroll
    for (int mf = 0; mf < 4; mf++)
#pragma unroll
        for (int nf = 0; nf < 4; nf++)
#pragma unroll
            for (int e = 0; e < 4; e++) acc[mf][nf][e] = 0.0f;

    // ---- stage one chunk window: 32 cpairs x 88 cp16 ----
    auto issueChunk = [&](int chunk) {
        const int cp0 = chunk * 32;
        const uint32_t dst = smb + (chunk * CHUNKW) * 4;
#pragma unroll
        for (int q = 0; q < 11; q++) {        // 2816 items / 256 threads = 11
            const int it = tid + q * 256;
            const int row = it / 88;
            const int col = it - row * 88;
            cp16(dst + (row * LDW + col * 4) * 4,
                 xim + (size_t)(cp0 + row) * PHW + abase + col * 4);
        }
    };

    const uint32_t* wf0 = g_wf + ((size_t)oct * 2 + wmg) * 512 + lane * 16;
    auto loadA1 = [&](int kt16, uint32_t a[16]) {   // one k16 -> 16 words
        const uint4* p = reinterpret_cast<const uint4*>(wf0 + (size_t)kt16 * 2048);
#pragma unroll
        for (int q = 0; q < 4; q++) {
            const uint4 v = p[q];
            a[q * 4 + 0] = v.x; a[q * 4 + 1] = v.y;
            a[q * 4 + 2] = v.z; a[q * 4 + 3] = v.w;
        }
    };

    issueChunk(0); CP_COMMIT;
    issueChunk(1); CP_COMMIT;

#pragma unroll
    for (int chunk = 0; chunk < 2; chunk++) {
        if (chunk == 0) { CP_WAIT(1); } else { CP_WAIT(0); }
        __syncthreads();
        const uint32_t* win = smW + chunk * CHUNKW;

#pragma unroll 1
        for (int tap = 0; tap < 9; tap++) {
            const int rr = tap / 3, sc = tap - rr * 3;
            const int toff = rr * 58 + sc;
#pragma unroll
            for (int h = 0; h < 4; h++) {        // k16 within tap
                uint32_t a[16];
                loadA1(chunk * 36 + tap * 4 + h, a);
                const int hrow = h * 8;
                uint32_t b[4][2];
#pragma unroll
                for (int nf = 0; nf < 4; nf++) {
                    b[nf][0] = win[(hrow + cq) * LDW + toff + pxr[nf]];
                    b[nf][1] = win[(hrow + cq + 4) * LDW + toff + pxr[nf]];
                }
#pragma unroll
                for (int mf = 0; mf < 4; mf++)
#pragma unroll
                    for (int nf = 0; nf < 4; nf++)
                        MMA16(acc[mf][nf], a + mf * 4, b[nf][0], b[nf][1]);
            }
        }
    }

    // ---- epilogue ----
    const size_t obase = (size_t)ni * COUT * HW;
#pragma unroll
    for (int mf = 0; mf < 4; mf++) {
        const int mg = oct * 128 + wmg * 64 + mf * 16 + r;
        const float b0 = __ldg(bias + mg);
        const float b1 = __ldg(bias + mg + 8);
        float* o0 = out + obase + (size_t)mg * HW;
#pragma unroll
        for (int nf = 0; nf < 4; nf++) {
            const int px = p0 + wn0 + nf * 8 + cq * 2;
            if (px < HW) {
                float2 v0 = make_float2(acc[mf][nf][0] + b0, acc[mf][nf][1] + b0);
                float2 v1 = make_float2(acc[mf][nf][2] + b1, acc[mf][nf][3] + b1);
                *reinterpret_cast<float2*>(o0 + px) = v0;
                *reinterpret_cast<float2*>(o0 + (size_t)8 * HW + px) = v1;
            }
        }
    }
}

extern "C" void kernel_launch(void* const* d_in, const int* in_sizes, int n_in,
                              void* d_out, int out_size)
{
    const float* x    = (const float*)d_in[0];
    const float* W    = (const float*)d_in[1];
    const float* bias = (const float*)d_in[2];
    float* out        = (float*)d_out;

    static bool attr_done = false;
    if (!attr_done) {
        cudaFuncSetAttribute(conv_mma, cudaFuncAttributeMaxDynamicSharedMemorySize,
                             SMEM_BYTES);
        attr_done = true;
    }

    wf_kernel<<<72 * 2 * 2 * 32 * 16 / 256, 256>>>(W);
    xh_kernel<<<32 * 64 * PHW / 256, 256>>>(x);

    dim3 grid(25, 32, 2);
    conv_mma<<<grid, 256, SMEM_BYTES>>>(bias, out);
}

// round 13
// speedup vs baseline: 1.2730x; 1.2730x over previous
#include <cuda_runtime.h>
#include <cuda_fp16.h>
#include <cstdint>

// Conv2d 3x3 s1 p1 via mma.sync m16n8k16 FP16 (f32 accum) implicit GEMM.
// CTA tile 128oc x 256px, 256 threads (8 warps, 64x64 warp tiles, same warp
// geometry as the 206.9us R11 kernel). K order: chunk(64ch), tap, k16; the 9
// taps of a chunk read one union window per channel-pair staged ONCE
// (32 cpairs x 472 words, stride 488). 2 syncs per CTA.
// A: prepass packs per-thread fragments (consumption order), LDG.128 pairwise
// register double-buffered. B: prepass packs fp16 channel-pairs, zero-padded.

#define HW    3136
#define PHW   3364            // 58*58
#define CIN   128
#define COUT  256
#define KTOT  1152
#define LDW   488             // window row stride (words); 488 mod 32 = 8
#define WCOLS 118             // cp16 per staged row (472 words)
#define CHUNKW (32*LDW)       // 15616 words per chunk window
#define SMEM_BYTES ((2*CHUNKW + 64)*4)   // 125184 B

#define WF_WORDS (72*2*2*32*16)          // 147456
#define WF_BLOCKS (WF_WORDS/256)         // 576
#define XH_BLOCKS (32*64*PHW/256)        // 26912

__device__ __align__(16) uint32_t g_wf[WF_WORDS];             // frags, consumption order
__device__ __align__(16) uint32_t g_xh[32 * 64 * PHW + 1024]; // packed fp16 x

// merged prepass: blocks [0,576) build weight fragments, rest pack x.
// wf word w: reg=w&3, mf=(w>>2)&3, lane=(w>>4)&31, wmg=(w>>9)&1, oct=(w>>10)&1,
//            kt16=w>>11 ; kt16 = chunk*36 + tap*4 + h ; c = chunk*64+h*16+klocal
__global__ void prep_kernel(const float* __restrict__ W, const float* __restrict__ x) {
    if (blockIdx.x < WF_BLOCKS) {
        const int w = blockIdx.x * 256 + threadIdx.x;
        const int reg = w & 3, mf = (w >> 2) & 3, lane = (w >> 4) & 31;
        const int wmg = (w >> 9) & 1, oct = (w >> 10) & 1, kt = w >> 11;
        const int chunk = kt / 36, rem = kt - chunk * 36;
        const int tap = rem >> 2, h = rem & 3;
        const int r = lane >> 2, cq = lane & 3;
        const int oc = oct * 128 + wmg * 64 + mf * 16 + r + (reg & 1) * 8;
        const int klocal = 2 * cq + ((reg & 2) ? 8 : 0);
        const int c = chunk * 64 + h * 16 + klocal;
        const __half2 hv = __floats2half2_rn(W[oc * KTOT + c * 9 + tap],
                                             W[oc * KTOT + (c + 1) * 9 + tap]);
        g_wf[w] = *reinterpret_cast<const uint32_t*>(&hv);
    } else {
        const int idx = (blockIdx.x - WF_BLOCKS) * 256 + threadIdx.x;
        const int cell = idx % PHW;
        const int cp = (idx / PHW) & 63;
        const int ni = idx / (PHW * 64);
        const int ph = cell / 58, pw = cell - ph * 58;
        float lo = 0.0f, hi = 0.0f;
        if (ph >= 1 && ph <= 56 && pw >= 1 && pw <= 56) {
            const size_t base = ((size_t)ni * CIN + 2 * cp) * HW + (ph - 1) * 56 + (pw - 1);
            lo = x[base];
            hi = x[base + HW];
        }
        const __half2 h = __floats2half2_rn(lo, hi);
        g_xh[idx] = *reinterpret_cast<const uint32_t*>(&h);
    }
}

__device__ __forceinline__ void cp16(uint32_t d, const void* s) {
    asm volatile("cp.async.cg.shared.global [%0], [%1], 16;" :: "r"(d), "l"(s));
}
#define CP_COMMIT asm volatile("cp.async.commit_group;" ::: "memory")
#define CP_WAIT(n) asm volatile("cp.async.wait_group %0;" :: "n"(n) : "memory")

#define MMA16(acc, a, b0, b1) \
    asm volatile("mma.sync.aligned.m16n8k16.row.col.f32.f16.f16.f32 " \
        "{%0,%1,%2,%3}, {%4,%5,%6,%7}, {%8,%9}, {%0,%1,%2,%3};" \
        : "+f"((acc)[0]), "+f"((acc)[1]), "+f"((acc)[2]), "+f"((acc)[3]) \
        : "r"((a)[0]), "r"((a)[1]), "r"((a)[2]), "r"((a)[3]), "r"(b0), "r"(b1))

__global__ void __launch_bounds__(256, 1)
conv_mma(const float* __restrict__ bias, float* __restrict__ out)
{
    extern __shared__ uint32_t smW[];
    const uint32_t smb = (uint32_t)__cvta_generic_to_shared(smW);
    const int tid  = threadIdx.x;
    const int lane = tid & 31;
    const int wid  = tid >> 5;            // 0..7
    const int r    = lane >> 2, cq = lane & 3;
    const int p0   = blockIdx.x * 256;    // 256-px tile
    const int ni   = blockIdx.y;
    const int oct  = blockIdx.z;
    const int wmg  = wid & 1;
    const int wn0  = (wid >> 1) * 64;     // 0,64,128,192

    const int oh0 = p0 / 56;
    const int abase = (oh0 * 58) & ~3;    // aligned window start in padded img
    const int am0   = oh0 * 58 - abase;   // 0..3

    // per-thread B pixel offsets relative to window start
    int pxr[8];
#pragma unroll
    for (int nf = 0; nf < 8; nf++) {
        int px = p0 + wn0 + nf * 8 + r;
        if (px >= HW) px = HW - 1;
        const int oh = px / 56, ow = px - oh * 56;
        pxr[nf] = oh * 58 + ow - oh0 * 58 + am0;
    }

    const uint32_t* xim = g_xh + (size_t)ni * (64 * PHW);

    float acc[4][8][4];
#pragma unroll
    for (int mf = 0; mf < 4; mf++)
#pragma unroll
        for (int nf = 0; nf < 8; nf++)
#pragma unroll
            for (int e = 0; e < 4; e++) acc[mf][nf][e] = 0.0f;

    // ---- stage one chunk window: 32 cpairs x 118 cp16 (3776 items) ----
    auto issueChunk = [&](int chunk) {
        const int cp0 = chunk * 32;
        const uint32_t dst = smb + (chunk * CHUNKW) * 4;
#pragma unroll
        for (int q = 0; q < 15; q++) {        // 3776 / 256 = 14.75
            const int it = tid + q * 256;
            if (q == 14 && it >= 3776) break;
            const int row = it / WCOLS;
            const int col = it - row * WCOLS;
            cp16(dst + (row * LDW + col * 4) * 4,
                 xim + (size_t)(cp0 + row) * PHW + abase + col * 4);
        }
    };

    const uint32_t* wf0 = g_wf + ((size_t)oct * 2 + wmg) * 512 + lane * 16;
    auto loadA2 = [&](int P, uint32_t a[32]) {    // pair P -> kt16 2P, 2P+1
        const uint4* p  = reinterpret_cast<const uint4*>(wf0 + (size_t)(2 * P) * 2048);
        const uint4* p2 = reinterpret_cast<const uint4*>(wf0 + (size_t)(2 * P + 1) * 2048);
#pragma unroll
        for (int q = 0; q < 4; q++) {
            const uint4 v = p[q];
            a[q * 4 + 0] = v.x; a[q * 4 + 1] = v.y; a[q * 4 + 2] = v.z; a[q * 4 + 3] = v.w;
        }
#pragma unroll
        for (int q = 0; q < 4; q++) {
            const uint4 v = p2[q];
            a[16 + q * 4 + 0] = v.x; a[16 + q * 4 + 1] = v.y;
            a[16 + q * 4 + 2] = v.z; a[16 + q * 4 + 3] = v.w;
        }
    };

    issueChunk(0); CP_COMMIT;
    issueChunk(1); CP_COMMIT;

    uint32_t Ab[2][32];
    loadA2(0, Ab[0]);

#pragma unroll
    for (int chunk = 0; chunk < 2; chunk++) {
        if (chunk == 0) { CP_WAIT(1); } else { CP_WAIT(0); }
        __syncthreads();
        const uint32_t* win = smW + chunk * CHUNKW;

#pragma unroll 1
        for (int tap = 0; tap < 9; tap++) {
            const int rr = tap / 3, sc = tap - rr * 3;
            const int toff = rr * 58 + sc;
#pragma unroll
            for (int sp = 0; sp < 2; sp++) {           // k16-pair within tap
                const int gpair = chunk * 18 + tap * 2 + sp;
                if (gpair + 1 < 36) loadA2(gpair + 1, Ab[sp ^ 1]);
#pragma unroll
                for (int h2 = 0; h2 < 2; h2++) {       // k16 within pair
                    const int hrow = (sp * 2 + h2) * 8;
                    uint32_t b[8][2];
#pragma unroll
                    for (int nf = 0; nf < 8; nf++) {
                        b[nf][0] = win[(hrow + cq) * LDW + toff + pxr[nf]];
                        b[nf][1] = win[(hrow + cq + 4) * LDW + toff + pxr[nf]];
                    }
                    const uint32_t* af = Ab[sp] + h2 * 16;
#pragma unroll
                    for (int mf = 0; mf < 4; mf++)
#pragma unroll
                        for (int nf = 0; nf < 8; nf++)
                            MMA16(acc[mf][nf], af + mf * 4, b[nf][0], b[nf][1]);
                }
            }
        }
    }

    // ---- epilogue ----
    const size_t obase = (size_t)ni * COUT * HW;
#pragma unroll
    for (int mf = 0; mf < 4; mf++) {
        const int mg = oct * 128 + wmg * 64 + mf * 16 + r;
        const float b0 = __ldg(bias + mg);
        const float b1 = __ldg(bias + mg + 8);
        float* o0 = out + obase + (size_t)mg * HW;
#pragma unroll
        for (int nf = 0; nf < 8; nf++) {
            const int px = p0 + wn0 + nf * 8 + cq * 2;
            if (px < HW) {
                float2 v0 = make_float2(acc[mf][nf][0] + b0, acc[mf][nf][1] + b0);
                float2 v1 = make_float2(acc[mf][nf][2] + b1, acc[mf][nf][3] + b1);
                *reinterpret_cast<float2*>(o0 + px) = v0;
                *reinterpret_cast<float2*>(o0 + (size_t)8 * HW + px) = v1;
            }
        }
    }
}

extern "C" void kernel_launch(void* const* d_in, const int* in_sizes, int n_in,
                              void* d_out, int out_size)
{
    const float* x    = (const float*)d_in[0];
    const float* W    = (const float*)d_in[1];
    const float* bias = (const float*)d_in[2];
    float* out        = (float*)d_out;

    static bool attr_done = false;
    if (!attr_done) {
        cudaFuncSetAttribute(conv_mma, cudaFuncAttributeMaxDynamicSharedMemorySize,
                             SMEM_BYTES);
        attr_done = true;
    }

    prep_kernel<<<WF_BLOCKS + XH_BLOCKS, 256>>>(W, x);

    dim3 grid(13, 32, 2);   // 13 px-tiles (256 px) x 32 img x 2 oc-halves
    conv_mma<<<grid, 256, SMEM_BYTES>>>(bias, out);
}

// round 14
// speedup vs baseline: 1.4933x; 1.1730x over previous
#include <cuda_runtime.h>
#include <cuda_fp16.h>
#include <cstdint>

// Conv2d 3x3 s1 p1 via mma.sync m16n8k16 FP16 (f32 accum) implicit GEMM.
// Main kernel = R11 (best: 206.9us total, main ~182us): 128-thread CTAs,
// CTA tile 128oc x 128px, 4 warps of 64x64. K order: chunk(64ch), tap, k16;
// per chunk one union window staged once (32 cpairs x 352 words, stride 360),
// 2 syncs per CTA. A: packed per-thread fragments via LDG.128, pairwise reg
// double-buffered. Prepass: single merged kernel (wf frags + vectorized
// interior x-pack) after a cudaMemsetAsync zeroes the padded x buffer.

#define HW    3136
#define PHW   3364            // 58*58
#define CIN   128
#define COUT  256
#define KTOT  1152
#define LDW   360             // window row stride (words); 360 mod 32 = 8
#define CHUNKW (32*LDW)       // 11520 words per chunk window
#define SMEM_BYTES ((2*CHUNKW + 64)*4)   // 92416 B

#define WF_WORDS  (72*2*2*32*16)         // 147456
#define WF_BLOCKS (WF_WORDS/256)         // 576
#define XH_ITEMS  (32*64*56*14)          // interior: 14 float4-groups per row
#define XH_BLOCKS (XH_ITEMS/256)         // 6272

__device__ __align__(16) uint32_t g_wf[WF_WORDS];             // frags, consumption order
__device__ __align__(16) uint32_t g_xh[32 * 64 * PHW + 1024]; // packed fp16 x (zeroed)

// merged prepass.
// wf word w: reg=w&3, mf=(w>>2)&3, lane=(w>>4)&31, wmg=(w>>9)&1, oct=(w>>10)&1,
//            kt16=w>>11 ; kt16 = chunk*36 + tap*4 + h ; c = chunk*64+h*16+klocal
__global__ void prep_kernel(const float* __restrict__ W, const float* __restrict__ x) {
    if (blockIdx.x < WF_BLOCKS) {
        const int w = blockIdx.x * 256 + threadIdx.x;
        const int reg = w & 3, mf = (w >> 2) & 3, lane = (w >> 4) & 31;
        const int wmg = (w >> 9) & 1, oct = (w >> 10) & 1, kt = w >> 11;
        const int chunk = kt / 36, rem = kt - chunk * 36;
        const int tap = rem >> 2, h = rem & 3;
        const int r = lane >> 2, cq = lane & 3;
        const int oc = oct * 128 + wmg * 64 + mf * 16 + r + (reg & 1) * 8;
        const int klocal = 2 * cq + ((reg & 2) ? 8 : 0);
        const int c = chunk * 64 + h * 16 + klocal;
        const __half2 hv = __floats2half2_rn(W[oc * KTOT + c * 9 + tap],
                                             W[oc * KTOT + (c + 1) * 9 + tap]);
        g_wf[w] = *reinterpret_cast<const uint32_t*>(&hv);
    } else {
        // interior x-pack: item = (cpni*56 + ph)*14 + g ; cpni = ni*64 + cp
        const int item = (blockIdx.x - WF_BLOCKS) * 256 + threadIdx.x;
        const int g = item % 14;
        const int t = item / 14;
        const int ph = t % 56;
        const int cpni = t / 56;
        const float* src = x + (size_t)2 * cpni * HW + ph * 56 + 4 * g;
        const float4 lo = __ldg(reinterpret_cast<const float4*>(src));
        const float4 hi = __ldg(reinterpret_cast<const float4*>(src + HW));
        uint32_t* dst = g_xh + (size_t)cpni * PHW + (ph + 1) * 58 + 1 + 4 * g;
        __half2 h0 = __floats2half2_rn(lo.x, hi.x);
        __half2 h1 = __floats2half2_rn(lo.y, hi.y);
        __half2 h2 = __floats2half2_rn(lo.z, hi.z);
        __half2 h3 = __floats2half2_rn(lo.w, hi.w);
        dst[0] = *reinterpret_cast<const uint32_t*>(&h0);
        dst[1] = *reinterpret_cast<const uint32_t*>(&h1);
        dst[2] = *reinterpret_cast<const uint32_t*>(&h2);
        dst[3] = *reinterpret_cast<const uint32_t*>(&h3);
    }
}

__device__ __forceinline__ void cp16(uint32_t d, const void* s) {
    asm volatile("cp.async.cg.shared.global [%0], [%1], 16;" :: "r"(d), "l"(s));
}
#define CP_COMMIT asm volatile("cp.async.commit_group;" ::: "memory")
#define CP_WAIT(n) asm volatile("cp.async.wait_group %0;" :: "n"(n) : "memory")

#define MMA16(acc, a, b0, b1) \
    asm volatile("mma.sync.aligned.m16n8k16.row.col.f32.f16.f16.f32 " \
        "{%0,%1,%2,%3}, {%4,%5,%6,%7}, {%8,%9}, {%0,%1,%2,%3};" \
        : "+f"((acc)[0]), "+f"((acc)[1]), "+f"((acc)[2]), "+f"((acc)[3]) \
        : "r"((a)[0]), "r"((a)[1]), "r"((a)[2]), "r"((a)[3]), "r"(b0), "r"(b1))

__global__ void __launch_bounds__(128, 2)
conv_mma(const float* __restrict__ bias, float* __restrict__ out)
{
    extern __shared__ uint32_t smW[];
    const uint32_t smb = (uint32_t)__cvta_generic_to_shared(smW);
    const int tid  = threadIdx.x;
    const int lane = tid & 31;
    const int wid  = tid >> 5;
    const int r    = lane >> 2, cq = lane & 3;
    const int p0   = blockIdx.x * 128;
    const int ni   = blockIdx.y;
    const int oct  = blockIdx.z;
    const int wmg  = wid & 1;
    const int wn0  = (wid >> 1) * 64;

    const int oh0 = p0 / 56;
    const int abase = (oh0 * 58) & ~3;
    const int am0   = oh0 * 58 - abase;

    int pxr[8];
#pragma unroll
    for (int nf = 0; nf < 8; nf++) {
        int px = p0 + wn0 + nf * 8 + r;
        if (px >= HW) px = HW - 1;
        const int oh = px / 56, ow = px - oh * 56;
        pxr[nf] = oh * 58 + ow - oh0 * 58 + am0;
    }

    const uint32_t* xim = g_xh + (size_t)ni * (64 * PHW);

    float acc[4][8][4];
#pragma unroll
    for (int mf = 0; mf < 4; mf++)
#pragma unroll
        for (int nf = 0; nf < 8; nf++)
#pragma unroll
            for (int e = 0; e < 4; e++) acc[mf][nf][e] = 0.0f;

    auto issueChunk = [&](int chunk) {
        const int cp0 = chunk * 32;
        const uint32_t dst = smb + (chunk * CHUNKW) * 4;
#pragma unroll
        for (int q = 0; q < 22; q++) {          // 2816 items / 128 threads
            const int it = tid + q * 128;
            const int row = it / 88;
            const int col = it - row * 88;
            cp16(dst + (row * LDW + col * 4) * 4,
                 xim + (size_t)(cp0 + row) * PHW + abase + col * 4);
        }
    };

    const uint32_t* wf0 = g_wf + ((size_t)oct * 2 + wmg) * 512 + lane * 16;
    auto loadA2 = [&](int P, uint32_t a[32]) {
        const uint4* p  = reinterpret_cast<const uint4*>(wf0 + (size_t)(2 * P) * 2048);
        const uint4* p2 = reinterpret_cast<const uint4*>(wf0 + (size_t)(2 * P + 1) * 2048);
#pragma unroll
        for (int q = 0; q < 4; q++) {
            const uint4 v = p[q];
            a[q * 4 + 0] = v.x; a[q * 4 + 1] = v.y; a[q * 4 + 2] = v.z; a[q * 4 + 3] = v.w;
        }
#pragma unroll
        for (int q = 0; q < 4; q++) {
            const uint4 v = p2[q];
            a[16 + q * 4 + 0] = v.x; a[16 + q * 4 + 1] = v.y;
            a[16 + q * 4 + 2] = v.z; a[16 + q * 4 + 3] = v.w;
        }
    };

    issueChunk(0); CP_COMMIT;
    issueChunk(1); CP_COMMIT;

    uint32_t Ab[2][32];
    loadA2(0, Ab[0]);

#pragma unroll
    for (int chunk = 0; chunk < 2; chunk++) {
        if (chunk == 0) { CP_WAIT(1); } else { CP_WAIT(0); }
        __syncthreads();
        const uint32_t* win = smW + chunk * CHUNKW;

#pragma unroll 1
        for (int tap = 0; tap < 9; tap++) {
            const int rr = tap / 3, sc = tap - rr * 3;
            const int toff = rr * 58 + sc;
#pragma unroll
            for (int sp = 0; sp < 2; sp++) {
                const int gpair = chunk * 18 + tap * 2 + sp;
                if (gpair + 1 < 36) loadA2(gpair + 1, Ab[sp ^ 1]);
#pragma unroll
                for (int h2 = 0; h2 < 2; h2++) {
                    const int hrow = (sp * 2 + h2) * 8;
                    uint32_t b[8][2];
#pragma unroll
                    for (int nf = 0; nf < 8; nf++) {
                        b[nf][0] = win[(hrow + cq) * LDW + toff + pxr[nf]];
                        b[nf][1] = win[(hrow + cq + 4) * LDW + toff + pxr[nf]];
                    }
                    const uint32_t* af = Ab[sp] + h2 * 16;
#pragma unroll
                    for (int mf = 0; mf < 4; mf++)
#pragma unroll
                        for (int nf = 0; nf < 8; nf++)
                            MMA16(acc[mf][nf], af + mf * 4, b[nf][0], b[nf][1]);
                }
            }
        }
    }

    const size_t obase = (size_t)ni * COUT * HW;
#pragma unroll
    for (int mf = 0; mf < 4; mf++) {
        const int mg = oct * 128 + wmg * 64 + mf * 16 + r;
        const float b0 = __ldg(bias + mg);
        const float b1 = __ldg(bias + mg + 8);
        float* o0 = out + obase + (size_t)mg * HW;
#pragma unroll
        for (int nf = 0; nf < 8; nf++) {
            const int px = p0 + wn0 + nf * 8 + cq * 2;
            if (px < HW) {
                float2 v0 = make_float2(acc[mf][nf][0] + b0, acc[mf][nf][1] + b0);
                float2 v1 = make_float2(acc[mf][nf][2] + b1, acc[mf][nf][3] + b1);
                *reinterpret_cast<float2*>(o0 + px) = v0;
                *reinterpret_cast<float2*>(o0 + (size_t)8 * HW + px) = v1;
            }
        }
    }
}

extern "C" void kernel_launch(void* const* d_in, const int* in_sizes, int n_in,
                              void* d_out, int out_size)
{
    const float* x    = (const float*)d_in[0];
    const float* W    = (const float*)d_in[1];
    const float* bias = (const float*)d_in[2];
    float* out        = (float*)d_out;

    static void* xh_addr = nullptr;
    if (!xh_addr) {
        cudaFuncSetAttribute(conv_mma, cudaFuncAttributeMaxDynamicSharedMemorySize,
                             SMEM_BYTES);
        cudaGetSymbolAddress(&xh_addr, g_xh);
    }

    cudaMemsetAsync(xh_addr, 0, sizeof(uint32_t) * (32 * 64 * PHW + 1024));
    prep_kernel<<<WF_BLOCKS + XH_BLOCKS, 256>>>(W, x);

    dim3 grid(25, 32, 2);
    conv_mma<<<grid, 128, SMEM_BYTES>>>(bias, out);
}